// round 16
// baseline (speedup 1.0000x reference)
#include <cuda_runtime.h>
#include <math.h>

#define FRAME      480
#define NHALF      480
#define FREQ       481
#define NB_ERB     32
#define NB_DF      96
#define ALPHA_F    0.99f
#define ONE_MINUS_ALPHA 0.01f
#define WNORM_F    (1.0f/960.0f)
#define T_MAX      65536
#define CHUNKS     2048
#define HALFCH     1024
#define PI_F       3.14159265358979f
#define ZP         17            // padded Z row stride in float2 (conflict-free)
#define NSEG_MAX   64

typedef unsigned long long ull;

// ---------------- packed f32x2 primitives ----------------
__device__ __forceinline__ ull pk(float x, float y){ ull r; asm("mov.b64 %0, {%1, %2};" : "=l"(r) : "f"(x), "f"(y)); return r; }
__device__ __forceinline__ void up(ull a, float& x, float& y){ asm("mov.b64 {%0, %1}, %2;" : "=f"(x), "=f"(y) : "l"(a)); }
__device__ __forceinline__ ull padd(ull a, ull b){ ull r; asm("add.rn.f32x2 %0, %1, %2;" : "=l"(r) : "l"(a), "l"(b)); return r; }
__device__ __forceinline__ ull psub(ull a, ull b){ ull r; asm("sub.rn.f32x2 %0, %1, %2;" : "=l"(r) : "l"(a), "l"(b)); return r; }
__device__ __forceinline__ ull pmul(ull a, ull b){ ull r; asm("mul.rn.f32x2 %0, %1, %2;" : "=l"(r) : "l"(a), "l"(b)); return r; }
__device__ __forceinline__ ull pfma(ull a, ull b, ull c){ ull r; asm("fma.rn.f32x2 %0, %1, %2, %3;" : "=l"(r) : "l"(a), "l"(b), "l"(c)); return r; }

__device__ __forceinline__ void cmulc2(ull& re, ull& im, float c, float s){
    ull C = pk(c, c), S = pk(s, s);
    ull nr = psub(pmul(re, C), pmul(im, S));
    ull ni = pfma(im, C, pmul(re, S));
    re = nr; im = ni;
}

// ---------------- compile-time trig (double Taylor, |x| <= ~pi) ----------------
constexpr double PI_D = 3.14159265358979323846;
constexpr double tsin(double x){
    double t = x, s = x;
    for (int n = 1; n <= 11; n++){ t *= -x*x/((2.0*n)*(2.0*n+1.0)); s += t; }
    return s;
}
constexpr double tcos(double x){
    double t = 1.0, s = 1.0;
    for (int n = 1; n <= 11; n++){ t *= -x*x/((2.0*n-1.0)*(2.0*n)); s += t; }
    return s;
}

struct TwBaseTab { float4 v[32]; };
constexpr TwBaseTab mk_twbase(){
    TwBaseTab t{};
    for (int l = 0; l < 32; l++){
        double ang = -2.0 * PI_D * (double)l / 480.0;
        float c = (float)tcos(ang), s = (float)tsin(ang);
        t.v[l] = { c, c, s, s };
    }
    return t;
}
struct ShtwTab { float2 v[96]; };
constexpr ShtwTab mk_shtw(){
    ShtwTab t{};
    for (int idx = 0; idx < 96; idx++){
        int j = idx / 32, l = idx % 32;
        int h = 16 >> j;
        if (l & h){
            double ang = -2.0 * PI_D * (double)(l & (h-1)) / (double)(2*h);
            t.v[idx] = { (float)tcos(ang), (float)tsin(ang) };
        } else {
            t.v[idx] = { 1.0f, 0.0f };
        }
    }
    return t;
}
struct WinTab { float2 v[NHALF]; };
constexpr WinTab mk_win2(){
    WinTab t{};
    const double sc = 0.5 / 960.0;
    for (int j = 0; j < NHALF; j++){
        double a0 = tsin(0.5 * PI_D * (2*j + 0.5) / 480.0);
        double a1 = tsin(0.5 * PI_D * (2*j + 1.5) / 480.0);
        t.v[j] = { (float)(sc * tsin(0.5 * PI_D * a0 * a0)),
                   (float)(sc * tsin(0.5 * PI_D * a1 * a1)) };
    }
    return t;
}
struct RecTab { float2 v[32]; };
constexpr RecTab mk_rec32(){
    RecTab t{};
    for (int l = 0; l < 32; l++){
        double ang = -PI_D * (double)l / 480.0;
        t.v[l] = { (float)tcos(ang), (float)tsin(ang) };
    }
    return t;
}
__device__ const TwBaseTab g_twbase_c = mk_twbase();
__device__ const ShtwTab   g_shtw_c   = mk_shtw();
__device__ const WinTab    g_win2_c   = mk_win2();
__device__ const RecTab    g_rec32_c  = mk_rec32();

// ---------------- compile-time ERB segmentation tables ----------------
struct SegTabs { unsigned mask[32]; int base[32]; int lo[32]; int hi[32]; };
constexpr SegTabs mk_segtabs(){
    SegTabs t{};
    const int off[32] = {0,2,4,6,8,10,12,14,16,18,20,22,24,26,31,36,43,50,58,68,
                         80,93,108,126,146,170,198,229,266,308,358,414};
    for (int b = 0; b < 32; b++){ t.lo[b] = 1<<30; t.hi[b] = -1; }
    int slot = 0;
    for (int l = 0; l < 32; l++){
        int nb = (l == 31) ? 16 : 15;
        unsigned mask = 0;
        t.base[l] = slot;
        for (int p = 0; p < nb; p++){
            int q = 15*l + p;
            bool bandEnd = (q == 480);
            for (int b = 1; b < 32; b++) if (q + 1 == off[b]) bandEnd = true;
            bool sliceEnd = (p == nb - 1);
            if (bandEnd || sliceEnd){
                mask |= (1u << p);
                int band = 31;
                for (int b = 0; b < 31; b++)
                    if (q >= off[b] && q < off[b+1]){ band = b; break; }
                if (slot < t.lo[band]) t.lo[band] = slot;
                if (slot + 1 > t.hi[band]) t.hi[band] = slot + 1;
                slot++;
            }
        }
        t.mask[l] = mask;
    }
    return t;
}
__device__ const SegTabs g_seg = mk_segtabs();

// ---------------- static device scratch ----------------
__device__ float  g_erb[T_MAX * NB_ERB];
__device__ float  g_mag[T_MAX * NB_DF];
__device__ float  g_carryE[CHUNKS * NB_ERB];
__device__ float  g_inE[CHUNKS * NB_ERB];
__device__ float  g_carryS[CHUNKS * NB_DF];
__device__ float  g_inS[CHUNKS * NB_DF];

__constant__ float c_bandInv[NB_ERB] =
 {0.5f,0.5f,0.5f,0.5f,0.5f,0.5f,0.5f,0.5f,0.5f,0.5f,0.5f,0.5f,0.5f,
  0.2f,0.2f,1.f/7,1.f/7,0.125f,0.1f,1.f/12,1.f/13,1.f/15,1.f/18,0.05f,
  1.f/24,1.f/28,1.f/31,1.f/37,1.f/42,0.02f,1.f/56,1.f/67};

// ---------------- packed Winograd DFTs ----------------
__device__ __forceinline__ void dft3p2(ull x0r, ull x0i, ull x1r, ull x1i, ull x2r, ull x2i,
                                       ull& X0r, ull& X0i, ull& X1r, ull& X1i, ull& X2r, ull& X2i){
    ull Ch = pk(-0.5f,-0.5f), C8 = pk(0.86602540378f,0.86602540378f);
    ull t1r = padd(x1r,x2r), t1i = padd(x1i,x2i);
    ull t2r = psub(x1r,x2r), t2i = psub(x1i,x2i);
    X0r = padd(x0r,t1r); X0i = padd(x0i,t1i);
    ull mr = pfma(Ch,t1r,x0r), mi = pfma(Ch,t1i,x0i);
    ull vr = pmul(C8,t2r),     vi = pmul(C8,t2i);
    X1r = padd(mr,vi); X1i = psub(mi,vr);
    X2r = psub(mr,vi); X2i = padd(mi,vr);
}
__device__ __forceinline__ void dft5p2(ull x0r, ull x0i, ull x1r, ull x1i, ull x2r, ull x2i,
                                       ull x3r, ull x3i, ull x4r, ull x4i,
                                       ull& X0r, ull& X0i, ull& X1r, ull& X1i, ull& X2r, ull& X2i,
                                       ull& X3r, ull& X3i, ull& X4r, ull& X4i){
    ull Cq = pk(-0.25f,-0.25f), C5 = pk(0.55901699437f,0.55901699437f);
    ull Cs1 = pk(0.95105651630f,0.95105651630f), Cs2 = pk(0.58778525229f,0.58778525229f);
    ull Cs1n = pk(-0.95105651630f,-0.95105651630f);
    ull t1r=padd(x1r,x4r), t1i=padd(x1i,x4i);
    ull t2r=psub(x1r,x4r), t2i=psub(x1i,x4i);
    ull t3r=padd(x2r,x3r), t3i=padd(x2i,x3i);
    ull t4r=psub(x2r,x3r), t4i=psub(x2i,x3i);
    ull t5r=padd(t1r,t3r), t5i=padd(t1i,t3i);
    X0r = padd(x0r,t5r); X0i = padd(x0i,t5i);
    ull pr = pfma(Cq,t5r,x0r), pi = pfma(Cq,t5i,x0i);
    ull t6r=psub(t1r,t3r), t6i=psub(t1i,t3i);
    ull qr = pmul(C5,t6r), qi = pmul(C5,t6i);
    ull Pr=padd(pr,qr), Pi=padd(pi,qi), Qr=psub(pr,qr), Qi=psub(pi,qi);
    ull Rr = pfma(Cs2,t4r,pmul(Cs1,t2r)), Ri = pfma(Cs2,t4i,pmul(Cs1,t2i));
    ull Sr = pfma(Cs1n,t4r,pmul(Cs2,t2r)), Si = pfma(Cs1n,t4i,pmul(Cs2,t2i));
    X1r=padd(Pr,Ri); X1i=psub(Pi,Rr);
    X4r=psub(Pr,Ri); X4i=padd(Pi,Rr);
    X2r=padd(Qr,Si); X2i=psub(Qi,Sr);
    X3r=psub(Qr,Si); X3i=padd(Qi,Sr);
}

// ---------------- scalar epilogue (padded Z, incremental rec, balanced ERB) ----------------
__device__ __forceinline__ void epilogue_frame(const float2* __restrict__ Z, float* __restrict__ mg,
                                               float* __restrict__ sPart,
                                               float2* __restrict__ out2, int t, int l,
                                               unsigned laneMask, int laneBase,
                                               int bandLo, int bandHi){
    size_t orow = (size_t)t * FREQ;
    float2 rc = g_rec32_c.v[l];               // cis(-pi*l/480)
    const float RC = 0.97814760073f, RS = -0.20791169082f;   // cis(-pi/15)
    for (int k = l; k <= 240; k += 32){
        int i1 = k + 2*(k/15);                // padded index
        int kc = (480 - k) % 480;
        int i2 = kc + 2*(kc/15);
        float2 Zk = Z[i1];
        float2 Zc = Z[i2];
        float Ex = Zk.x + Zc.x, Ey = Zk.y - Zc.y;
        float Ox = Zk.y + Zc.y, Oy = Zc.x - Zk.x;
        float wOx = fmaf(rc.x, Ox, -rc.y*Oy);
        float wOy = fmaf(rc.x, Oy,  rc.y*Ox);
        float X1x = Ex + wOx, X1y = Ey + wOy;
        float X2x = Ex - wOx, X2y = wOy - Ey;
        out2[orow + k]       = make_float2(X1x, X1y);
        out2[orow + 480 - k] = make_float2(X2x, X2y);
        float m1 = fmaf(X1x, X1x, X1y*X1y);
        float m2 = fmaf(X2x, X2x, X2y*X2y);
        mg[k]       = m1;
        mg[480 - k] = m2;
        if (k < NB_DF) g_mag[(size_t)t * NB_DF + k] = sqrtf(m1);
        float nrx = fmaf(rc.x, RC, -rc.y*RS);
        float nry = fmaf(rc.x, RS,  rc.y*RC);
        rc = make_float2(nrx, nry);
    }
    __syncwarp();
    // balanced ERB phase 1
    {
        int base = 15 * l;
        float acc = 0.0f;
        int slot = laneBase;
        #pragma unroll
        for (int p = 0; p < 16; p++){
            if (p < 15 || l == 31){
                acc += mg[base + p];
                if ((laneMask >> p) & 1u){
                    sPart[slot++] = acc;
                    acc = 0.0f;
                }
            }
        }
    }
    __syncwarp();
    // phase 2
    {
        float acc = 0.0f;
        for (int s = bandLo; s < bandHi; s++) acc += sPart[s];
        g_erb[(size_t)t * NB_ERB + l] = 10.0f * __log10f(fmaf(acc, c_bandInv[l], 1e-10f));
    }
}

// ---------------- FFT: one warp per FRAME-PAIR, f32x2 packed ----------------
__global__ __launch_bounds__(128, 7) void fft_kernel(const float* __restrict__ audio,
                                                     float* __restrict__ out, int T){
    __shared__ float2 sZ[4][32*ZP];
    __shared__ float  smag[4][FREQ];
    __shared__ float  sPartBuf[4][NSEG_MAX];
    int w = threadIdx.x >> 5;
    int l = threadIdx.x & 31;
    int g = blockIdx.x * 4 + w;
    int ta = 2 * g;
    if (ta >= T) return;
    bool liveB = (ta + 1 < T);

    unsigned laneMask = g_seg.mask[l];
    int laneBase = g_seg.base[l];
    int bandLo = g_seg.lo[l];
    int bandHi = g_seg.hi[l];

    const float2* audio2 = (const float2*)audio;
    long baseA = ((long)ta - 1) * 240;
    long baseB = baseA + 240;

    ull re[15], im[15];
    #pragma unroll
    for (int m = 0; m < 15; m++){
        int n = l + 32*m;
        long iA = baseA + n, iB = baseB + n;
        float2 xa = (iA >= 0) ? audio2[iA] : make_float2(0.f,0.f);
        float2 xb = (liveB)  ? audio2[iB] : make_float2(0.f,0.f);
        float2 ww = g_win2_c.v[n];
        re[m] = pmul(pk(xa.x, xb.x), pk(ww.x, ww.x));
        im[m] = pmul(pk(xa.y, xb.y), pk(ww.y, ww.y));
    }

    ull Br[15], Bi[15];
    {
        ull G0r[5], G0i[5], G1r[5], G1i[5], G2r[5], G2i[5];
        #pragma unroll
        for (int b = 0; b < 5; b++)
            dft3p2(re[b],im[b], re[5+b],im[5+b], re[10+b],im[10+b],
                   G0r[b],G0i[b], G1r[b],G1i[b], G2r[b],G2i[b]);
        dft5p2(G0r[0],G0i[0],G0r[1],G0i[1],G0r[2],G0i[2],G0r[3],G0i[3],G0r[4],G0i[4],
               Br[0],Bi[0], Br[3],Bi[3], Br[6],Bi[6], Br[9],Bi[9], Br[12],Bi[12]);
        cmulc2(G1r[1],G1i[1],  0.91354545764f,-0.40673664308f);
        cmulc2(G1r[2],G1i[2],  0.66913060636f,-0.74314482548f);
        cmulc2(G1r[3],G1i[3],  0.30901699437f,-0.95105651630f);
        cmulc2(G1r[4],G1i[4], -0.10452846327f,-0.99452189537f);
        dft5p2(G1r[0],G1i[0],G1r[1],G1i[1],G1r[2],G1i[2],G1r[3],G1i[3],G1r[4],G1i[4],
               Br[1],Bi[1], Br[4],Bi[4], Br[7],Bi[7], Br[10],Bi[10], Br[13],Bi[13]);
        cmulc2(G2r[1],G2i[1],  0.66913060636f,-0.74314482548f);
        cmulc2(G2r[2],G2i[2], -0.10452846327f,-0.99452189537f);
        cmulc2(G2r[3],G2i[3], -0.80901699437f,-0.58778525229f);
        cmulc2(G2r[4],G2i[4], -0.97814760073f,  0.20791169082f);
        dft5p2(G2r[0],G2i[0],G2r[1],G2i[1],G2r[2],G2i[2],G2r[3],G2i[3],G2r[4],G2i[4],
               Br[2],Bi[2], Br[5],Bi[5], Br[8],Bi[8], Br[11],Bi[11], Br[14],Bi[14]);
    }

    // ---- four-step twiddle: incremental powers of W480^l
    {
        float4 tb = g_twbase_c.v[l];
        ull bc = pk(tb.x, tb.y), bs = pk(tb.z, tb.w);
        ull cc = bc, cs = bs;
        #pragma unroll
        for (int k1 = 1; k1 < 15; k1++){
            ull nr = psub(pmul(Br[k1], cc), pmul(Bi[k1], cs));
            ull ni = pfma(Bi[k1], cc, pmul(Br[k1], cs));
            Br[k1] = nr; Bi[k1] = ni;
            if (k1 < 14){
                ull t1 = psub(pmul(cc, bc), pmul(cs, bs));
                cs = pfma(cs, bc, pmul(cc, bs));
                cc = t1;
            }
        }
    }

    bool rot3 = ((l & 3) == 3);
    ull NEG1 = pk(-1.f, -1.f);
    #pragma unroll
    for (int j = 0; j < 5; j++){
        int h = 16 >> j;
        float sgn = (l & h) ? -1.f : 1.f;
        ull sgn2 = pk(sgn, sgn);
        ull C = 0, S = 0, Sn = 0;
        if (j < 3){
            float2 tw = g_shtw_c.v[j*32 + l];
            C = pk(tw.x, tw.x); S = pk(tw.y, tw.y); Sn = pk(-tw.y, -tw.y);
        }
        #pragma unroll
        for (int k1 = 0; k1 < 15; k1++){
            float ra, rb, ia, ib;
            up(Br[k1], ra, rb); up(Bi[k1], ia, ib);
            float pra = __shfl_xor_sync(0xffffffffu, ra, h);
            float prb = __shfl_xor_sync(0xffffffffu, rb, h);
            float pia = __shfl_xor_sync(0xffffffffu, ia, h);
            float pib = __shfl_xor_sync(0xffffffffu, ib, h);
            ull nr = pfma(sgn2, Br[k1], pk(pra, prb));
            ull ni = pfma(sgn2, Bi[k1], pk(pia, pib));
            if (j < 3){
                Br[k1] = pfma(ni, Sn, pmul(nr, C));
                Bi[k1] = pfma(ni, C,  pmul(nr, S));
            } else if (j == 3){
                Br[k1] = rot3 ? ni : nr;
                Bi[k1] = rot3 ? pmul(NEG1, nr) : ni;
            } else {
                Br[k1] = nr; Bi[k1] = ni;
            }
        }
    }

    int s = ((l&1)<<4) | ((l&2)<<2) | (l&4) | ((l&8)>>2) | ((l&16)>>4);
    int zoff = ZP * s;
    float2* Z = sZ[w];
    float* mg = smag[w];
    float* sPart = sPartBuf[w];
    float2* out2 = (float2*)out;

    #pragma unroll
    for (int k1 = 0; k1 < 15; k1++){
        float ra, rb, ia, ib;
        up(Br[k1], ra, rb); up(Bi[k1], ia, ib);
        Z[zoff + k1] = make_float2(ra, ia);
    }
    __syncwarp();
    epilogue_frame(Z, mg, sPart, out2, ta, l, laneMask, laneBase, bandLo, bandHi);
    __syncwarp();

    if (liveB){
        #pragma unroll
        for (int k1 = 0; k1 < 15; k1++){
            float ra, rb, ia, ib;
            up(Br[k1], ra, rb); up(Bi[k1], ia, ib);
            Z[zoff + k1] = make_float2(rb, ib);
        }
        __syncwarp();
        epilogue_frame(Z, mg, sPart, out2, ta + 1, l, laneMask, laneBase, bandLo, bandHi);
    }
}

// ---------------- chunked scans ----------------
__global__ void pass1(int T){
    int w = blockIdx.x * blockDim.x + threadIdx.x;
    int len = T / CHUNKS;
    int totE = CHUNKS * NB_ERB;
    if (w < totE){
        int ch = w % NB_ERB, c = w / NB_ERB;
        const float* x = g_erb + (size_t)c * len * NB_ERB + ch;
        float s = 0.0f;
        for (int i = 0; i < len; i++) s = ALPHA_F * s + ONE_MINUS_ALPHA * x[i * NB_ERB];
        g_carryE[c * NB_ERB + ch] = s;
    } else if (w < totE + CHUNKS * NB_DF){
        int w2 = w - totE;
        int ch = w2 % NB_DF, c = w2 / NB_DF;
        const float* x = g_mag + (size_t)c * len * NB_DF + ch;
        float u = 0.0f;
        for (int i = 0; i < len; i++) u = ALPHA_F * u + ONE_MINUS_ALPHA * x[i * NB_DF];
        g_carryS[c * NB_DF + ch] = u;
    }
}

__global__ __launch_bounds__(HALFCH) void pass2(int T){
    __shared__ float wa[32], wb[32];
    int ch = blockIdx.x;
    int c  = threadIdx.x;
    int lane = c & 31, wid = c >> 5;
    int len = T / CHUNKS;
    float m = __powf(ALPHA_F, (float)len);
    bool isErb = (ch < NB_ERB);
    int cc = isErb ? ch : (ch - NB_ERB);
    float cr0 = isErb ? g_carryE[(2*c)   * NB_ERB + cc] : g_carryS[(2*c)   * NB_DF + cc];
    float cr1 = isErb ? g_carryE[(2*c+1) * NB_ERB + cc] : g_carryS[(2*c+1) * NB_DF + cc];

    float a = m * m, b = fmaf(m, cr0, cr1);
    #pragma unroll
    for (int off = 1; off < 32; off <<= 1){
        float pa = __shfl_up_sync(0xffffffffu, a, off);
        float pb = __shfl_up_sync(0xffffffffu, b, off);
        if (lane >= off){ b = fmaf(a, pb, b); a = a * pa; }
    }
    if (lane == 31){ wa[wid] = a; wb[wid] = b; }
    __syncthreads();
    if (wid == 0){
        float ca = wa[lane], cb = wb[lane];
        #pragma unroll
        for (int off = 1; off < 32; off <<= 1){
            float pa = __shfl_up_sync(0xffffffffu, ca, off);
            float pb = __shfl_up_sync(0xffffffffu, cb, off);
            if (lane >= off){ cb = fmaf(ca, pb, cb); ca = ca * pa; }
        }
        wa[lane] = ca; wb[lane] = cb;
    }
    __syncthreads();
    float Wa = (wid == 0) ? 1.f : wa[wid-1];
    float Wb = (wid == 0) ? 0.f : wb[wid-1];
    float ea = __shfl_up_sync(0xffffffffu, a, 1);
    float eb = __shfl_up_sync(0xffffffffu, b, 1);
    if (lane == 0){ ea = 1.f; eb = 0.f; }
    float Aex = ea * Wa;
    float Bex = fmaf(ea, Wb, eb);

    if (isErb){
        float s0 = -60.0f - 30.0f * (float)cc / 31.0f;
        float st0 = Aex * s0 + Bex;
        g_inE[(2*c)   * NB_ERB + cc] = st0;
        g_inE[(2*c+1) * NB_ERB + cc] = fmaf(m, st0, cr0);
    } else {
        float u0 = 0.001f - 0.0009f * (float)cc / 95.0f;
        float st0 = Aex * u0 + Bex;
        g_inS[(2*c)   * NB_DF + cc] = st0;
        g_inS[(2*c+1) * NB_DF + cc] = fmaf(m, st0, cr0);
    }
}

__global__ void pass3(float* __restrict__ out, int T){
    int w = blockIdx.x * blockDim.x + threadIdx.x;
    int len = T / CHUNKS;
    int totE = CHUNKS * NB_ERB;
    if (w < totE){
        int ch = w % NB_ERB, c = w / NB_ERB;
        size_t erb_off = (size_t)T * 962;
        const float* x = g_erb + (size_t)c * len * NB_ERB + ch;
        float* o = out + erb_off + (size_t)c * len * NB_ERB + ch;
        float s = g_inE[c * NB_ERB + ch];
        for (int i = 0; i < len; i++){
            float xv = x[i * NB_ERB];
            s = ALPHA_F * s + ONE_MINUS_ALPHA * xv;
            o[i * NB_ERB] = (xv - s) * 0.025f;
        }
    } else if (w < totE + CHUNKS * NB_DF){
        int w2 = w - totE;
        int ch = w2 % NB_DF, c = w2 / NB_DF;
        const float* mgp = g_mag + (size_t)c * len * NB_DF + ch;
        const float2* sp2 = (const float2*)out + (size_t)c * len * FREQ + ch;
        float2* o2 = (float2*)(out + (size_t)T * 962 + (size_t)T * NB_ERB)
                     + (size_t)c * len * NB_DF + ch;
        float u = g_inS[c * NB_DF + ch];
        for (int i = 0; i < len; i++){
            u = ALPHA_F * u + ONE_MINUS_ALPHA * mgp[i * NB_DF];
            float r = rsqrtf(u);
            float2 sv = sp2[i * FREQ];
            o2[i * NB_DF] = make_float2(sv.x * r, sv.y * r);
        }
    }
}

// ---------------- launch ----------------
extern "C" void kernel_launch(void* const* d_in, const int* in_sizes, int n_in,
                              void* d_out, int out_size){
    const float* audio = (const float*)d_in[0];
    float* out = (float*)d_out;
    int T = in_sizes[0] / FRAME;
    if (T > T_MAX) T = T_MAX;
    int scanThreads = CHUNKS * (NB_ERB + NB_DF);
    int nPairs = (T + 1) / 2;

    fft_kernel<<<(nPairs + 3) / 4, 128>>>(audio, out, T);
    pass1<<<(scanThreads + 255) / 256, 256>>>(T);
    pass2<<<NB_ERB + NB_DF, HALFCH>>>(T);
    pass3<<<(scanThreads + 255) / 256, 256>>>(out, T);
}

// round 17
// speedup vs baseline: 1.0538x; 1.0538x over previous
#include <cuda_runtime.h>
#include <math.h>

#define FRAME      480
#define NHALF      480
#define FREQ       481
#define NB_ERB     32
#define NB_DF      96
#define ALPHA_F    0.99f
#define ONE_MINUS_ALPHA 0.01f
#define WNORM_F    (1.0f/960.0f)
#define T_MAX      65536
#define CHUNKS     2048
#define HALFCH     1024
#define PI_F       3.14159265358979f
#define ZP         17            // padded Z row stride in float2 (conflict-free)
#define NSEG_MAX   64

typedef unsigned long long ull;

// ---------------- packed f32x2 primitives ----------------
__device__ __forceinline__ ull pk(float x, float y){ ull r; asm("mov.b64 %0, {%1, %2};" : "=l"(r) : "f"(x), "f"(y)); return r; }
__device__ __forceinline__ void up(ull a, float& x, float& y){ asm("mov.b64 {%0, %1}, %2;" : "=f"(x), "=f"(y) : "l"(a)); }
__device__ __forceinline__ ull padd(ull a, ull b){ ull r; asm("add.rn.f32x2 %0, %1, %2;" : "=l"(r) : "l"(a), "l"(b)); return r; }
__device__ __forceinline__ ull psub(ull a, ull b){ ull r; asm("sub.rn.f32x2 %0, %1, %2;" : "=l"(r) : "l"(a), "l"(b)); return r; }
__device__ __forceinline__ ull pmul(ull a, ull b){ ull r; asm("mul.rn.f32x2 %0, %1, %2;" : "=l"(r) : "l"(a), "l"(b)); return r; }
__device__ __forceinline__ ull pfma(ull a, ull b, ull c){ ull r; asm("fma.rn.f32x2 %0, %1, %2, %3;" : "=l"(r) : "l"(a), "l"(b), "l"(c)); return r; }

__device__ __forceinline__ void cmulc2(ull& re, ull& im, float c, float s){
    ull C = pk(c, c), S = pk(s, s);
    ull nr = psub(pmul(re, C), pmul(im, S));
    ull ni = pfma(im, C, pmul(re, S));
    re = nr; im = ni;
}

// ---------------- compile-time trig (double Taylor, |x| <= ~pi) ----------------
constexpr double PI_D = 3.14159265358979323846;
constexpr double tsin(double x){
    double t = x, s = x;
    for (int n = 1; n <= 11; n++){ t *= -x*x/((2.0*n)*(2.0*n+1.0)); s += t; }
    return s;
}
constexpr double tcos(double x){
    double t = 1.0, s = 1.0;
    for (int n = 1; n <= 11; n++){ t *= -x*x/((2.0*n-1.0)*(2.0*n)); s += t; }
    return s;
}

struct TwBaseTab { float4 v[32]; };
constexpr TwBaseTab mk_twbase(){
    TwBaseTab t{};
    for (int l = 0; l < 32; l++){
        double ang = -2.0 * PI_D * (double)l / 480.0;
        float c = (float)tcos(ang), s = (float)tsin(ang);
        t.v[l] = { c, c, s, s };
    }
    return t;
}
struct ShtwTab { float2 v[96]; };
constexpr ShtwTab mk_shtw(){
    ShtwTab t{};
    for (int idx = 0; idx < 96; idx++){
        int j = idx / 32, l = idx % 32;
        int h = 16 >> j;
        if (l & h){
            double ang = -2.0 * PI_D * (double)(l & (h-1)) / (double)(2*h);
            t.v[idx] = { (float)tcos(ang), (float)tsin(ang) };
        } else {
            t.v[idx] = { 1.0f, 0.0f };
        }
    }
    return t;
}
struct WinTab { float2 v[NHALF]; };
constexpr WinTab mk_win2(){
    WinTab t{};
    const double sc = 0.5 / 960.0;
    for (int j = 0; j < NHALF; j++){
        double a0 = tsin(0.5 * PI_D * (2*j + 0.5) / 480.0);
        double a1 = tsin(0.5 * PI_D * (2*j + 1.5) / 480.0);
        t.v[j] = { (float)(sc * tsin(0.5 * PI_D * a0 * a0)),
                   (float)(sc * tsin(0.5 * PI_D * a1 * a1)) };
    }
    return t;
}
struct RecTab { float2 v[32]; };
constexpr RecTab mk_rec32(){
    RecTab t{};
    for (int l = 0; l < 32; l++){
        double ang = -PI_D * (double)l / 480.0;
        t.v[l] = { (float)tcos(ang), (float)tsin(ang) };
    }
    return t;
}
__device__ const TwBaseTab g_twbase_c = mk_twbase();
__device__ const ShtwTab   g_shtw_c   = mk_shtw();
__device__ const WinTab    g_win2_c   = mk_win2();
__device__ const RecTab    g_rec32_c  = mk_rec32();

// ---------------- compile-time ERB segmentation tables ----------------
struct SegTabs { unsigned mask[32]; int base[32]; int lo[32]; int hi[32]; };
constexpr SegTabs mk_segtabs(){
    SegTabs t{};
    const int off[32] = {0,2,4,6,8,10,12,14,16,18,20,22,24,26,31,36,43,50,58,68,
                         80,93,108,126,146,170,198,229,266,308,358,414};
    for (int b = 0; b < 32; b++){ t.lo[b] = 1<<30; t.hi[b] = -1; }
    int slot = 0;
    for (int l = 0; l < 32; l++){
        int nb = (l == 31) ? 16 : 15;
        unsigned mask = 0;
        t.base[l] = slot;
        for (int p = 0; p < nb; p++){
            int q = 15*l + p;
            bool bandEnd = (q == 480);
            for (int b = 1; b < 32; b++) if (q + 1 == off[b]) bandEnd = true;
            bool sliceEnd = (p == nb - 1);
            if (bandEnd || sliceEnd){
                mask |= (1u << p);
                int band = 31;
                for (int b = 0; b < 31; b++)
                    if (q >= off[b] && q < off[b+1]){ band = b; break; }
                if (slot < t.lo[band]) t.lo[band] = slot;
                if (slot + 1 > t.hi[band]) t.hi[band] = slot + 1;
                slot++;
            }
        }
        t.mask[l] = mask;
    }
    return t;
}
__device__ const SegTabs g_seg = mk_segtabs();

// ---------------- static device scratch ----------------
__device__ float  g_erb[T_MAX * NB_ERB];
__device__ float  g_mag[T_MAX * NB_DF];
__device__ float  g_carryE[CHUNKS * NB_ERB];
__device__ float  g_inE[CHUNKS * NB_ERB];
__device__ float  g_carryS[CHUNKS * NB_DF];
__device__ float  g_inS[CHUNKS * NB_DF];

__constant__ float c_bandInv[NB_ERB] =
 {0.5f,0.5f,0.5f,0.5f,0.5f,0.5f,0.5f,0.5f,0.5f,0.5f,0.5f,0.5f,0.5f,
  0.2f,0.2f,1.f/7,1.f/7,0.125f,0.1f,1.f/12,1.f/13,1.f/15,1.f/18,0.05f,
  1.f/24,1.f/28,1.f/31,1.f/37,1.f/42,0.02f,1.f/56,1.f/67};

// ---------------- packed Winograd DFTs ----------------
__device__ __forceinline__ void dft3p2(ull x0r, ull x0i, ull x1r, ull x1i, ull x2r, ull x2i,
                                       ull& X0r, ull& X0i, ull& X1r, ull& X1i, ull& X2r, ull& X2i){
    ull Ch = pk(-0.5f,-0.5f), C8 = pk(0.86602540378f,0.86602540378f);
    ull t1r = padd(x1r,x2r), t1i = padd(x1i,x2i);
    ull t2r = psub(x1r,x2r), t2i = psub(x1i,x2i);
    X0r = padd(x0r,t1r); X0i = padd(x0i,t1i);
    ull mr = pfma(Ch,t1r,x0r), mi = pfma(Ch,t1i,x0i);
    ull vr = pmul(C8,t2r),     vi = pmul(C8,t2i);
    X1r = padd(mr,vi); X1i = psub(mi,vr);
    X2r = psub(mr,vi); X2i = padd(mi,vr);
}
__device__ __forceinline__ void dft5p2(ull x0r, ull x0i, ull x1r, ull x1i, ull x2r, ull x2i,
                                       ull x3r, ull x3i, ull x4r, ull x4i,
                                       ull& X0r, ull& X0i, ull& X1r, ull& X1i, ull& X2r, ull& X2i,
                                       ull& X3r, ull& X3i, ull& X4r, ull& X4i){
    ull Cq = pk(-0.25f,-0.25f), C5 = pk(0.55901699437f,0.55901699437f);
    ull Cs1 = pk(0.95105651630f,0.95105651630f), Cs2 = pk(0.58778525229f,0.58778525229f);
    ull Cs1n = pk(-0.95105651630f,-0.95105651630f);
    ull t1r=padd(x1r,x4r), t1i=padd(x1i,x4i);
    ull t2r=psub(x1r,x4r), t2i=psub(x1i,x4i);
    ull t3r=padd(x2r,x3r), t3i=padd(x2i,x3i);
    ull t4r=psub(x2r,x3r), t4i=psub(x2i,x3i);
    ull t5r=padd(t1r,t3r), t5i=padd(t1i,t3i);
    X0r = padd(x0r,t5r); X0i = padd(x0i,t5i);
    ull pr = pfma(Cq,t5r,x0r), pi = pfma(Cq,t5i,x0i);
    ull t6r=psub(t1r,t3r), t6i=psub(t1i,t3i);
    ull qr = pmul(C5,t6r), qi = pmul(C5,t6i);
    ull Pr=padd(pr,qr), Pi=padd(pi,qi), Qr=psub(pr,qr), Qi=psub(pi,qi);
    ull Rr = pfma(Cs2,t4r,pmul(Cs1,t2r)), Ri = pfma(Cs2,t4i,pmul(Cs1,t2i));
    ull Sr = pfma(Cs1n,t4r,pmul(Cs2,t2r)), Si = pfma(Cs1n,t4i,pmul(Cs2,t2i));
    X1r=padd(Pr,Ri); X1i=psub(Pi,Rr);
    X4r=psub(Pr,Ri); X4i=padd(Pi,Rr);
    X2r=padd(Qr,Si); X2i=psub(Qi,Sr);
    X3r=psub(Qr,Si); X3i=padd(Qi,Sr);
}

// ---------------- scalar epilogue (padded Z, incremental rec, balanced ERB) ----------------
__device__ __forceinline__ void epilogue_frame(const float2* __restrict__ Z, float* __restrict__ mg,
                                               float* __restrict__ sPart,
                                               float2* __restrict__ out2, int t, int l,
                                               unsigned laneMask, int laneBase,
                                               int bandLo, int bandHi){
    size_t orow = (size_t)t * FREQ;
    float2 rc = g_rec32_c.v[l];               // cis(-pi*l/480)
    const float RC = 0.97814760073f, RS = -0.20791169082f;   // cis(-pi/15)
    for (int k = l; k <= 240; k += 32){
        int i1 = k + 2*(k/15);                // padded index
        int kc = (480 - k) % 480;
        int i2 = kc + 2*(kc/15);
        float2 Zk = Z[i1];
        float2 Zc = Z[i2];
        float Ex = Zk.x + Zc.x, Ey = Zk.y - Zc.y;
        float Ox = Zk.y + Zc.y, Oy = Zc.x - Zk.x;
        float wOx = fmaf(rc.x, Ox, -rc.y*Oy);
        float wOy = fmaf(rc.x, Oy,  rc.y*Ox);
        float X1x = Ex + wOx, X1y = Ey + wOy;
        float X2x = Ex - wOx, X2y = wOy - Ey;
        out2[orow + k]       = make_float2(X1x, X1y);
        out2[orow + 480 - k] = make_float2(X2x, X2y);
        float m1 = fmaf(X1x, X1x, X1y*X1y);
        float m2 = fmaf(X2x, X2x, X2y*X2y);
        mg[k]       = m1;
        mg[480 - k] = m2;
        if (k < NB_DF) g_mag[(size_t)t * NB_DF + k] = sqrtf(m1);
        float nrx = fmaf(rc.x, RC, -rc.y*RS);
        float nry = fmaf(rc.x, RS,  rc.y*RC);
        rc = make_float2(nrx, nry);
    }
    __syncwarp();
    // balanced ERB phase 1
    {
        int base = 15 * l;
        float acc = 0.0f;
        int slot = laneBase;
        #pragma unroll
        for (int p = 0; p < 16; p++){
            if (p < 15 || l == 31){
                acc += mg[base + p];
                if ((laneMask >> p) & 1u){
                    sPart[slot++] = acc;
                    acc = 0.0f;
                }
            }
        }
    }
    __syncwarp();
    // phase 2
    {
        float acc = 0.0f;
        for (int s = bandLo; s < bandHi; s++) acc += sPart[s];
        g_erb[(size_t)t * NB_ERB + l] = 10.0f * __log10f(fmaf(acc, c_bandInv[l], 1e-10f));
    }
}

// ---------------- FFT: one warp per FRAME-PAIR, f32x2 packed ----------------
__global__ __launch_bounds__(128, 6) void fft_kernel(const float* __restrict__ audio,
                                                     float* __restrict__ out, int T){
    __shared__ float2 sZ[4][32*ZP];
    __shared__ float  smag[4][FREQ];
    __shared__ float  sPartBuf[4][NSEG_MAX];
    int w = threadIdx.x >> 5;
    int l = threadIdx.x & 31;
    int g = blockIdx.x * 4 + w;
    int ta = 2 * g;
    if (ta >= T) return;
    bool liveB = (ta + 1 < T);

    unsigned laneMask = g_seg.mask[l];
    int laneBase = g_seg.base[l];
    int bandLo = g_seg.lo[l];
    int bandHi = g_seg.hi[l];

    const float2* audio2 = (const float2*)audio;
    long baseA = ((long)ta - 1) * 240;
    long baseB = baseA + 240;

    ull re[15], im[15];
    #pragma unroll
    for (int m = 0; m < 15; m++){
        int n = l + 32*m;
        long iA = baseA + n, iB = baseB + n;
        float2 xa = (iA >= 0) ? audio2[iA] : make_float2(0.f,0.f);
        float2 xb = (liveB)  ? audio2[iB] : make_float2(0.f,0.f);
        float2 ww = g_win2_c.v[n];
        re[m] = pmul(pk(xa.x, xb.x), pk(ww.x, ww.x));
        im[m] = pmul(pk(xa.y, xb.y), pk(ww.y, ww.y));
    }

    ull Br[15], Bi[15];
    {
        ull G0r[5], G0i[5], G1r[5], G1i[5], G2r[5], G2i[5];
        #pragma unroll
        for (int b = 0; b < 5; b++)
            dft3p2(re[b],im[b], re[5+b],im[5+b], re[10+b],im[10+b],
                   G0r[b],G0i[b], G1r[b],G1i[b], G2r[b],G2i[b]);
        dft5p2(G0r[0],G0i[0],G0r[1],G0i[1],G0r[2],G0i[2],G0r[3],G0i[3],G0r[4],G0i[4],
               Br[0],Bi[0], Br[3],Bi[3], Br[6],Bi[6], Br[9],Bi[9], Br[12],Bi[12]);
        cmulc2(G1r[1],G1i[1],  0.91354545764f,-0.40673664308f);
        cmulc2(G1r[2],G1i[2],  0.66913060636f,-0.74314482548f);
        cmulc2(G1r[3],G1i[3],  0.30901699437f,-0.95105651630f);
        cmulc2(G1r[4],G1i[4], -0.10452846327f,-0.99452189537f);
        dft5p2(G1r[0],G1i[0],G1r[1],G1i[1],G1r[2],G1i[2],G1r[3],G1i[3],G1r[4],G1i[4],
               Br[1],Bi[1], Br[4],Bi[4], Br[7],Bi[7], Br[10],Bi[10], Br[13],Bi[13]);
        cmulc2(G2r[1],G2i[1],  0.66913060636f,-0.74314482548f);
        cmulc2(G2r[2],G2i[2], -0.10452846327f,-0.99452189537f);
        cmulc2(G2r[3],G2i[3], -0.80901699437f,-0.58778525229f);
        cmulc2(G2r[4],G2i[4], -0.97814760073f,  0.20791169082f);
        dft5p2(G2r[0],G2i[0],G2r[1],G2i[1],G2r[2],G2i[2],G2r[3],G2i[3],G2r[4],G2i[4],
               Br[2],Bi[2], Br[5],Bi[5], Br[8],Bi[8], Br[11],Bi[11], Br[14],Bi[14]);
    }

    // ---- four-step twiddle: incremental powers of W480^l
    {
        float4 tb = g_twbase_c.v[l];
        ull bc = pk(tb.x, tb.y), bs = pk(tb.z, tb.w);
        ull cc = bc, cs = bs;
        #pragma unroll
        for (int k1 = 1; k1 < 15; k1++){
            ull nr = psub(pmul(Br[k1], cc), pmul(Bi[k1], cs));
            ull ni = pfma(Bi[k1], cc, pmul(Br[k1], cs));
            Br[k1] = nr; Bi[k1] = ni;
            if (k1 < 14){
                ull t1 = psub(pmul(cc, bc), pmul(cs, bs));
                cs = pfma(cs, bc, pmul(cc, bs));
                cc = t1;
            }
        }
    }

    bool rot3 = ((l & 3) == 3);
    ull NEG1 = pk(-1.f, -1.f);
    #pragma unroll
    for (int j = 0; j < 5; j++){
        int h = 16 >> j;
        float sgn = (l & h) ? -1.f : 1.f;
        ull sgn2 = pk(sgn, sgn);
        ull C = 0, S = 0, Sn = 0;
        if (j < 3){
            float2 tw = g_shtw_c.v[j*32 + l];
            C = pk(tw.x, tw.x); S = pk(tw.y, tw.y); Sn = pk(-tw.y, -tw.y);
        }
        #pragma unroll
        for (int k1 = 0; k1 < 15; k1++){
            float ra, rb, ia, ib;
            up(Br[k1], ra, rb); up(Bi[k1], ia, ib);
            float pra = __shfl_xor_sync(0xffffffffu, ra, h);
            float prb = __shfl_xor_sync(0xffffffffu, rb, h);
            float pia = __shfl_xor_sync(0xffffffffu, ia, h);
            float pib = __shfl_xor_sync(0xffffffffu, ib, h);
            ull nr = pfma(sgn2, Br[k1], pk(pra, prb));
            ull ni = pfma(sgn2, Bi[k1], pk(pia, pib));
            if (j < 3){
                Br[k1] = pfma(ni, Sn, pmul(nr, C));
                Bi[k1] = pfma(ni, C,  pmul(nr, S));
            } else if (j == 3){
                Br[k1] = rot3 ? ni : nr;
                Bi[k1] = rot3 ? pmul(NEG1, nr) : ni;
            } else {
                Br[k1] = nr; Bi[k1] = ni;
            }
        }
    }

    int s = ((l&1)<<4) | ((l&2)<<2) | (l&4) | ((l&8)>>2) | ((l&16)>>4);
    int zoff = ZP * s;
    float2* Z = sZ[w];
    float* mg = smag[w];
    float* sPart = sPartBuf[w];
    float2* out2 = (float2*)out;

    #pragma unroll
    for (int k1 = 0; k1 < 15; k1++){
        float ra, rb, ia, ib;
        up(Br[k1], ra, rb); up(Bi[k1], ia, ib);
        Z[zoff + k1] = make_float2(ra, ia);
    }
    __syncwarp();
    epilogue_frame(Z, mg, sPart, out2, ta, l, laneMask, laneBase, bandLo, bandHi);
    __syncwarp();

    if (liveB){
        #pragma unroll
        for (int k1 = 0; k1 < 15; k1++){
            float ra, rb, ia, ib;
            up(Br[k1], ra, rb); up(Bi[k1], ia, ib);
            Z[zoff + k1] = make_float2(rb, ib);
        }
        __syncwarp();
        epilogue_frame(Z, mg, sPart, out2, ta + 1, l, laneMask, laneBase, bandLo, bandHi);
    }
}

// ---------------- chunked scans ----------------
__global__ void pass1(int T){
    int w = blockIdx.x * blockDim.x + threadIdx.x;
    int len = T / CHUNKS;
    int totE = CHUNKS * NB_ERB;
    if (w < totE){
        int ch = w % NB_ERB, c = w / NB_ERB;
        const float* x = g_erb + (size_t)c * len * NB_ERB + ch;
        float s = 0.0f;
        for (int i = 0; i < len; i++) s = ALPHA_F * s + ONE_MINUS_ALPHA * x[i * NB_ERB];
        g_carryE[c * NB_ERB + ch] = s;
    } else if (w < totE + CHUNKS * NB_DF){
        int w2 = w - totE;
        int ch = w2 % NB_DF, c = w2 / NB_DF;
        const float* x = g_mag + (size_t)c * len * NB_DF + ch;
        float u = 0.0f;
        for (int i = 0; i < len; i++) u = ALPHA_F * u + ONE_MINUS_ALPHA * x[i * NB_DF];
        g_carryS[c * NB_DF + ch] = u;
    }
}

__global__ __launch_bounds__(HALFCH) void pass2(int T){
    __shared__ float wa[32], wb[32];
    int ch = blockIdx.x;
    int c  = threadIdx.x;
    int lane = c & 31, wid = c >> 5;
    int len = T / CHUNKS;
    float m = __powf(ALPHA_F, (float)len);
    bool isErb = (ch < NB_ERB);
    int cc = isErb ? ch : (ch - NB_ERB);
    float cr0 = isErb ? g_carryE[(2*c)   * NB_ERB + cc] : g_carryS[(2*c)   * NB_DF + cc];
    float cr1 = isErb ? g_carryE[(2*c+1) * NB_ERB + cc] : g_carryS[(2*c+1) * NB_DF + cc];

    float a = m * m, b = fmaf(m, cr0, cr1);
    #pragma unroll
    for (int off = 1; off < 32; off <<= 1){
        float pa = __shfl_up_sync(0xffffffffu, a, off);
        float pb = __shfl_up_sync(0xffffffffu, b, off);
        if (lane >= off){ b = fmaf(a, pb, b); a = a * pa; }
    }
    if (lane == 31){ wa[wid] = a; wb[wid] = b; }
    __syncthreads();
    if (wid == 0){
        float ca = wa[lane], cb = wb[lane];
        #pragma unroll
        for (int off = 1; off < 32; off <<= 1){
            float pa = __shfl_up_sync(0xffffffffu, ca, off);
            float pb = __shfl_up_sync(0xffffffffu, cb, off);
            if (lane >= off){ cb = fmaf(ca, pb, cb); ca = ca * pa; }
        }
        wa[lane] = ca; wb[lane] = cb;
    }
    __syncthreads();
    float Wa = (wid == 0) ? 1.f : wa[wid-1];
    float Wb = (wid == 0) ? 0.f : wb[wid-1];
    float ea = __shfl_up_sync(0xffffffffu, a, 1);
    float eb = __shfl_up_sync(0xffffffffu, b, 1);
    if (lane == 0){ ea = 1.f; eb = 0.f; }
    float Aex = ea * Wa;
    float Bex = fmaf(ea, Wb, eb);

    if (isErb){
        float s0 = -60.0f - 30.0f * (float)cc / 31.0f;
        float st0 = Aex * s0 + Bex;
        g_inE[(2*c)   * NB_ERB + cc] = st0;
        g_inE[(2*c+1) * NB_ERB + cc] = fmaf(m, st0, cr0);
    } else {
        float u0 = 0.001f - 0.0009f * (float)cc / 95.0f;
        float st0 = Aex * u0 + Bex;
        g_inS[(2*c)   * NB_DF + cc] = st0;
        g_inS[(2*c+1) * NB_DF + cc] = fmaf(m, st0, cr0);
    }
}

__global__ void pass3(float* __restrict__ out, int T){
    int w = blockIdx.x * blockDim.x + threadIdx.x;
    int len = T / CHUNKS;
    int totE = CHUNKS * NB_ERB;
    if (w < totE){
        int ch = w % NB_ERB, c = w / NB_ERB;
        size_t erb_off = (size_t)T * 962;
        const float* x = g_erb + (size_t)c * len * NB_ERB + ch;
        float* o = out + erb_off + (size_t)c * len * NB_ERB + ch;
        float s = g_inE[c * NB_ERB + ch];
        for (int i = 0; i < len; i++){
            float xv = x[i * NB_ERB];
            s = ALPHA_F * s + ONE_MINUS_ALPHA * xv;
            o[i * NB_ERB] = (xv - s) * 0.025f;
        }
    } else if (w < totE + CHUNKS * NB_DF){
        int w2 = w - totE;
        int ch = w2 % NB_DF, c = w2 / NB_DF;
        const float* mgp = g_mag + (size_t)c * len * NB_DF + ch;
        const float2* sp2 = (const float2*)out + (size_t)c * len * FREQ + ch;
        float2* o2 = (float2*)(out + (size_t)T * 962 + (size_t)T * NB_ERB)
                     + (size_t)c * len * NB_DF + ch;
        float u = g_inS[c * NB_DF + ch];
        for (int i = 0; i < len; i++){
            u = ALPHA_F * u + ONE_MINUS_ALPHA * mgp[i * NB_DF];
            float r = rsqrtf(u);
            float2 sv = sp2[i * FREQ];
            o2[i * NB_DF] = make_float2(sv.x * r, sv.y * r);
        }
    }
}

// ---------------- launch ----------------
extern "C" void kernel_launch(void* const* d_in, const int* in_sizes, int n_in,
                              void* d_out, int out_size){
    const float* audio = (const float*)d_in[0];
    float* out = (float*)d_out;
    int T = in_sizes[0] / FRAME;
    if (T > T_MAX) T = T_MAX;
    int scanThreads = CHUNKS * (NB_ERB + NB_DF);
    int nPairs = (T + 1) / 2;

    fft_kernel<<<(nPairs + 3) / 4, 128>>>(audio, out, T);
    pass1<<<(scanThreads + 255) / 256, 256>>>(T);
    pass2<<<NB_ERB + NB_DF, HALFCH>>>(T);
    pass3<<<(scanThreads + 255) / 256, 256>>>(out, T);
}